// round 3
// baseline (speedup 1.0000x reference)
#include <cuda_runtime.h>
#include <math.h>

#define NB 48
#define CC 512
#define PP 1600
#define KK 64
#define EPSV 1e-12f

// Scratch (device globals; no allocations allowed)
__device__ float g_w[NB * KK * PP];      // soft_assign * hmp   [n][k][p]
__device__ float g_invn[NB * PP];        // 1/max(||x||, eps) per pixel
__device__ float g_hmp[NB * PP];         // attention heatmap per pixel
__device__ float g_wsum[NB * KK];        // sum_p w
__device__ float g_knss[NB * KK];        // per-(n,k) sumsq of normalized cluster vec

// ---------------------------------------------------------------------------
// K1: per-pixel channel stats: invn and heatmap. One coalesced pass over x.
// ---------------------------------------------------------------------------
__global__ void k_pixstats(const float* __restrict__ x,
                           const float* __restrict__ aw,
                           const float* __restrict__ ab) {
    __shared__ float saw[CC];
    int t = threadIdx.x;
    for (int i = t; i < CC; i += 256) saw[i] = aw[i];
    __syncthreads();

    int pix = blockIdx.x * 256 + t;              // 76800 total = 300 * 256
    int n = pix / PP;
    int p = pix - n * PP;
    const float* xp = x + (size_t)n * CC * PP + p;

    float ss = 0.f, av = 0.f;
#pragma unroll 8
    for (int c = 0; c < CC; c++) {
        float v = xp[(size_t)c * PP];
        ss = fmaf(v, v, ss);
        float r = v > 0.f ? v : 0.f;
        av = fmaf(r, saw[c], av);
    }
    float hm = av + ab[0];
    hm = hm > 0.f ? hm : 0.f;
    float invn = 1.f / fmaxf(sqrtf(ss), EPSV);
    g_invn[pix] = invn;
    g_hmp[pix] = hm;
}

// ---------------------------------------------------------------------------
// K2: logits GEMM [64k x 512c] x [512c x 128p tile] + softmax over k + w.
// 256 threads, micro-tile 4k x 8p per thread. Grid (13 p-tiles, 48 n).
// ---------------------------------------------------------------------------
__global__ void k_assign(const float* __restrict__ x,
                         const float* __restrict__ cw) {
    __shared__ float ws[16][65];      // [c-chunk][k]   (padded vs transpose writes)
    __shared__ float xs[16][128];     // [c-chunk][p]   (reused for softmax reductions)
    __shared__ float cm[128];
    __shared__ float cs[128];

    int t = threadIdx.x;
    int ty = t >> 4;                  // 0..15  -> k = ty + 16*i
    int tx = t & 15;                  // 0..15  -> p = tx + 16*j
    int n = blockIdx.y;
    int p0 = blockIdx.x * 128;
    const float* xb = x + (size_t)n * CC * PP;

    float acc[4][8];
#pragma unroll
    for (int i = 0; i < 4; i++)
#pragma unroll
        for (int j = 0; j < 8; j++) acc[i][j] = 0.f;

    for (int c0 = 0; c0 < CC; c0 += 16) {
#pragma unroll
        for (int q = 0; q < 4; q++) {            // conv_w tile: 64k x 16c
            int e = t + q * 256;
            int k = e >> 4, cc = e & 15;
            ws[cc][k] = cw[k * CC + c0 + cc];
        }
#pragma unroll
        for (int q = 0; q < 8; q++) {            // x tile: 16c x 128p
            int e = t + q * 256;
            int cc = e >> 7, pp = e & 127;
            int p = p0 + pp;
            xs[cc][pp] = (p < PP) ? xb[(size_t)(c0 + cc) * PP + p] : 0.f;
        }
        __syncthreads();
#pragma unroll
        for (int cc = 0; cc < 16; cc++) {
            float a[4], b[8];
#pragma unroll
            for (int i = 0; i < 4; i++) a[i] = ws[cc][ty + 16 * i];
#pragma unroll
            for (int j = 0; j < 8; j++) b[j] = xs[cc][tx + 16 * j];
#pragma unroll
            for (int i = 0; i < 4; i++)
#pragma unroll
                for (int j = 0; j < 8; j++) acc[i][j] = fmaf(a[i], b[j], acc[i][j]);
        }
        __syncthreads();
    }

    // logits = dot * invn[p]
    float inv[8], hm[8];
#pragma unroll
    for (int j = 0; j < 8; j++) {
        int p = p0 + tx + 16 * j;
        bool v = p < PP;
        inv[j] = v ? g_invn[n * PP + p] : 0.f;
        hm[j]  = v ? g_hmp[n * PP + p] : 0.f;
    }
#pragma unroll
    for (int i = 0; i < 4; i++)
#pragma unroll
        for (int j = 0; j < 8; j++) acc[i][j] *= inv[j];

    // softmax over k (64 vals split: 16 ty-rows x 4 per thread)
#pragma unroll
    for (int j = 0; j < 8; j++) {
        float m = acc[0][j];
#pragma unroll
        for (int i = 1; i < 4; i++) m = fmaxf(m, acc[i][j]);
        xs[ty][tx + 16 * j] = m;
    }
    __syncthreads();
    if (t < 128) {
        float m = -1e30f;
#pragma unroll
        for (int r = 0; r < 16; r++) m = fmaxf(m, xs[r][t]);
        cm[t] = m;
    }
    __syncthreads();
#pragma unroll
    for (int j = 0; j < 8; j++) {
        float m = cm[tx + 16 * j];
        float s = 0.f;
#pragma unroll
        for (int i = 0; i < 4; i++) {
            acc[i][j] = __expf(acc[i][j] - m);
            s += acc[i][j];
        }
        xs[ty][tx + 16 * j] = s;
    }
    __syncthreads();
    if (t < 128) {
        float s = 0.f;
#pragma unroll
        for (int r = 0; r < 16; r++) s += xs[r][t];
        cs[t] = s;
    }
    __syncthreads();

    float* wb = g_w + (size_t)n * KK * PP;
#pragma unroll
    for (int j = 0; j < 8; j++) {
        int p = p0 + tx + 16 * j;
        if (p < PP) {
            float f = hm[j] / cs[tx + 16 * j];
#pragma unroll
            for (int i = 0; i < 4; i++)
                wb[(size_t)(ty + 16 * i) * PP + p] = acc[i][j] * f;
        }
    }
}

// ---------------------------------------------------------------------------
// K3: term1 GEMM: [64k x 1600p] x [1600p x 128c tile] -> term1[k,c];
// invn folded into x side; wsum computed by c-tile-0 blocks. Grid (4, 48).
// ---------------------------------------------------------------------------
__global__ void k_vladgemm(const float* __restrict__ x,
                           float* __restrict__ out) {
    __shared__ float ws2[16][65];     // [p-chunk][k]
    __shared__ float xs2[16][129];    // [p-chunk][c]
    __shared__ float invs[PP];

    int t = threadIdx.x;
    int ty = t >> 4, tx = t & 15;
    int cb = blockIdx.x, n = blockIdx.y;
    int c0 = cb * 128;
    const float* xb = x + (size_t)n * CC * PP;
    const float* wb = g_w + (size_t)n * KK * PP;

    for (int i = t; i < PP; i += 256) invs[i] = g_invn[n * PP + i];

    float acc[4][8];
#pragma unroll
    for (int i = 0; i < 4; i++)
#pragma unroll
        for (int j = 0; j < 8; j++) acc[i][j] = 0.f;
    float wl = 0.f;
    __syncthreads();

    for (int p0 = 0; p0 < PP; p0 += 16) {
#pragma unroll
        for (int q = 0; q < 4; q++) {            // w tile: 64k x 16p (transposed)
            int e = t + q * 256;
            int k = e >> 4, pp = e & 15;
            ws2[pp][k] = wb[(size_t)k * PP + p0 + pp];
        }
#pragma unroll
        for (int q = 0; q < 8; q++) {            // x tile: 128c x 16p (transposed, scaled)
            int e = t + q * 256;
            int cl = e >> 4, pp = e & 15;
            xs2[pp][cl] = xb[(size_t)(c0 + cl) * PP + p0 + pp] * invs[p0 + pp];
        }
        __syncthreads();
        if (cb == 0 && t < 64) {
#pragma unroll
            for (int pp = 0; pp < 16; pp++) wl += ws2[pp][t];
        }
#pragma unroll
        for (int pp = 0; pp < 16; pp++) {
            float a[4], b[8];
#pragma unroll
            for (int i = 0; i < 4; i++) a[i] = ws2[pp][ty + 16 * i];
#pragma unroll
            for (int j = 0; j < 8; j++) b[j] = xs2[pp][tx + 16 * j];
#pragma unroll
            for (int i = 0; i < 4; i++)
#pragma unroll
                for (int j = 0; j < 8; j++) acc[i][j] = fmaf(a[i], b[j], acc[i][j]);
        }
        __syncthreads();
    }

    float* ob = out + (size_t)n * KK * CC;
#pragma unroll
    for (int i = 0; i < 4; i++)
#pragma unroll
        for (int j = 0; j < 8; j++)
            ob[(size_t)(ty + 16 * i) * CC + c0 + tx + 16 * j] = acc[i][j];
    if (cb == 0 && t < 64) g_wsum[n * KK + t] = wl;
}

// ---------------------------------------------------------------------------
// K4: vlad = term1 - wsum*centroid, intra-L2-norm per (n,k). 3072 blocks x 128.
// ---------------------------------------------------------------------------
__global__ void k_intranorm(float* __restrict__ out,
                            const float* __restrict__ cent) {
    int nk = blockIdx.x;
    int k = nk & 63;
    int t = threadIdx.x;
    float wsv = g_wsum[nk];
    size_t base = (size_t)nk * CC;
    const float* cb = cent + (size_t)k * CC;

    float v[4];
    float ss = 0.f;
#pragma unroll
    for (int q = 0; q < 4; q++) {
        int c = t + 128 * q;
        v[q] = out[base + c] - wsv * cb[c];
        ss = fmaf(v[q], v[q], ss);
    }
#pragma unroll
    for (int o = 16; o > 0; o >>= 1) ss += __shfl_xor_sync(0xffffffffu, ss, o);
    __shared__ float sred[4];
    if ((t & 31) == 0) sred[t >> 5] = ss;
    __syncthreads();
    float tot = sred[0] + sred[1] + sred[2] + sred[3];
    float invv = 1.f / fmaxf(sqrtf(tot), EPSV);
#pragma unroll
    for (int q = 0; q < 4; q++) out[base + t + 128 * q] = v[q] * invv;
    if (t == 0) g_knss[nk] = tot * invv * invv;
}

// ---------------------------------------------------------------------------
// K5: global L2 norm per n. Grid (48, 16), 2048 elems per block.
// ---------------------------------------------------------------------------
__global__ void k_globalnorm(float* __restrict__ out) {
    int n = blockIdx.x, t = threadIdx.x;
    float gs = 0.f;
#pragma unroll
    for (int i = 0; i < KK; i++) gs += g_knss[n * KK + i];
    float sc = 1.f / fmaxf(sqrtf(gs), EPSV);
    size_t base = (size_t)n * KK * CC + (size_t)blockIdx.y * 2048;
#pragma unroll
    for (int q = 0; q < 8; q++) out[base + t + 256 * q] *= sc;
}

// ---------------------------------------------------------------------------
extern "C" void kernel_launch(void* const* d_in, const int* in_sizes, int n_in,
                              void* d_out, int out_size) {
    const float* x  = (const float*)d_in[0];   // [48,512,40,40]
    const float* cw = (const float*)d_in[1];   // [64,512]
    const float* aw = (const float*)d_in[2];   // [1,512]
    const float* ab = (const float*)d_in[3];   // [1]
    const float* ct = (const float*)d_in[4];   // [64,512]
    float* out = (float*)d_out;                // [48, 32768]

    k_pixstats<<<300, 256>>>(x, aw, ab);
    k_assign<<<dim3(13, 48), 256>>>(x, cw);
    k_vladgemm<<<dim3(4, 48), 256>>>(x, out);
    k_intranorm<<<NB * KK, 128>>>(out, ct);
    k_globalnorm<<<dim3(48, 16), 256>>>(out);
}